// round 13
// baseline (speedup 1.0000x reference)
#include <cuda_runtime.h>
#include <math.h>

// ---------------------------------------------------------------------------
// SimplifiedIFEBranch — R13: R7 fc pipeline (best known) + 4x-distributed
// histogram binning (atomic merge + last-CTA normalize via ticket), keeping
// 3 grid barriers. Raw-bin buffer self-re-zeroed each launch.
// ---------------------------------------------------------------------------

#define NBINS 32
#define NCTA  128

// dynamic smem layout (floats)
#define W1_OFF 0            // 32 x 768  = 24576 floats (96 KB)
#define W2_OFF 24576        // 16 x 256  =  4096 floats (16 KB)
#define W3_OFF 28672        //  2 x 512  =  1024 floats ( 4 KB)
#define SMEM_FLOATS 29696
#define SMEM_BYTES  (SMEM_FLOATS * 4)

__device__ __forceinline__ float c_LO() { return (float)(-3.2 - (6.4 / 256.0) / 2.0); }
__device__ __forceinline__ float c_HI() { return (float)( 3.2 - (6.4 / 256.0) / 2.0); }
__device__ __forceinline__ float c_BW() {
    return (float)(((3.2 - (6.4 / 256.0) / 2.0) - (-3.2 - (6.4 / 256.0) / 2.0)) / 32.0);
}

// Scratch (__device__ globals; no allocation). Pair-packed layouts:
// buf[(k>>1)*64 + b*2 + (k&1)]
__device__ float g_hraw[3072 * 32];        // raw merged bins (zero-init, self-rezeroed)
__device__ float g_histP[3072 * 32];       // normalized
__device__ float g_x1T[1024 * 32];         // [n][b] accum, bias-preinit
__device__ float g_x2T[512 * 32];
__device__ unsigned int g_ticket[32];      // per-image arrival tickets (self-reset)
__device__ unsigned int g_bar_count = 0;
__device__ unsigned int g_bar_gen   = 0;

// ---- packed f32x2 helpers ---------------------------------------------------
__device__ __forceinline__ unsigned long long pack2(float x, float y) {
    unsigned long long r;
    asm("mov.b64 %0, {%1, %2};" : "=l"(r) : "f"(x), "f"(y));
    return r;
}
__device__ __forceinline__ void ffma2(unsigned long long& d,
                                      unsigned long long a, unsigned long long b) {
    asm("fma.rn.f32x2 %0, %1, %2, %0;" : "+l"(d) : "l"(a), "l"(b));
}
__device__ __forceinline__ float unpack_sum(unsigned long long p) {
    float lo, hi;
    asm("mov.b64 {%0, %1}, %2;" : "=f"(lo), "=f"(hi) : "l"(p));
    return lo + hi;
}

// ---- software grid barrier ----------------------------------------------------
__device__ __forceinline__ void grid_barrier() {
    __syncthreads();
    if (threadIdx.x == 0) {
        unsigned gen = *(volatile unsigned*)&g_bar_gen;
        __threadfence();
        unsigned old = atomicAdd(&g_bar_count, 1u);
        if (old == NCTA - 1) {
            g_bar_count = 0;
            __threadfence();
            atomicAdd(&g_bar_gen, 1u);
        } else {
            while (*(volatile unsigned*)&g_bar_gen == gen) { __nanosleep(32); }
        }
        __threadfence();
    }
    __syncthreads();
}

// ---- histogram helper -----------------------------------------------------------
__device__ __forceinline__ void hist_add(float* h, float Iu, float Iv, float w) {
    const float LO = c_LO(), HI = c_HI(), BW = c_BW();
    if (Iu >= LO && Iu <= HI && Iv >= LO && Iv <= HI) {
        int iu = (int)floorf((Iu - LO) / BW);
        int iv = (int)floorf((Iv - LO) / BW);
        iu = min(max(iu, 0), NBINS - 1);
        iv = min(max(iv, 0), NBINS - 1);
        atomicAdd(&h[iu * NBINS + iv], w);
    }
}

// ---- coalesced W tile stage (global -> smem), each element once ----------------
template <int ROWS, int COLS>
__device__ __forceinline__ void stage_tile(float* dst, const float* src, int ld) {
    constexpr int F4 = ROWS * COLS / 4;
    constexpr int RF = COLS / 4;
    #pragma unroll
    for (int f = threadIdx.x; f < F4; f += 512) {
        const int row = f / RF, col = f - row * RF;
        float4 v = __ldcg(reinterpret_cast<const float4*>(src + (size_t)row * ld + col * 4));
        reinterpret_cast<float4*>(dst)[f] = v;
    }
}

// ---- FC compute (W tile already in smem) — identical to R7 -----------------------
template <int KS, int NROWS, int NT, int NG, int KG, int HALVES,
          bool RELU_IN, bool PACKED_A, bool ATOMIC_OUT>
__device__ __forceinline__ void fc_compute(const float* __restrict__ AT,
                                           const float* wtile,
                                           const float* __restrict__ bias,
                                           float* __restrict__ dest, int ldo,
                                           float* scratch, int n0, int K0) {
    constexpr int CH = KS / KG;
    constexpr int NK = CH / HALVES;
    const int tid  = threadIdx.x;
    const int lane = tid & 31;
    const int w    = tid >> 5;
    const int kg   = w / NG;
    const int ng   = w % NG;

    unsigned long long acc2[NT];
    #pragma unroll
    for (int t = 0; t < NT; ++t) acc2[t] = 0ull;

    const int kbase = K0 + kg * CH;
    const float* wrow0 = wtile + (size_t)(ng * NT) * KS + kg * CH;

    #pragma unroll
    for (int h = 0; h < HALVES; ++h) {
        const int kh = kbase + h * NK;
        unsigned long long ap[NK / 2];
        if (PACKED_A) {
            const unsigned long long* src =
                reinterpret_cast<const unsigned long long*>(AT)
                + (size_t)(kh >> 1) * 32 + lane;
            #pragma unroll
            for (int j = 0; j < NK / 2; ++j) ap[j] = __ldcg(src + (size_t)j * 32);
        } else {
            #pragma unroll
            for (int j = 0; j < NK / 2; ++j) {
                float a0 = __ldcg(AT + (size_t)(kh + 2 * j) * 32 + lane);
                float a1 = __ldcg(AT + (size_t)(kh + 2 * j + 1) * 32 + lane);
                if (RELU_IN) { a0 = fmaxf(a0, 0.f); a1 = fmaxf(a1, 0.f); }
                ap[j] = pack2(a0, a1);
            }
        }
        #pragma unroll
        for (int j2 = 0; j2 < NK / 4; ++j2) {
            #pragma unroll
            for (int t = 0; t < NT; ++t) {
                ulonglong2 wv = *reinterpret_cast<const ulonglong2*>(
                    wrow0 + (size_t)t * KS + h * NK + 4 * j2);
                ffma2(acc2[t], wv.x, ap[2 * j2]);
                ffma2(acc2[t], wv.y, ap[2 * j2 + 1]);
            }
        }
    }
    __syncthreads();

    #pragma unroll
    for (int t = 0; t < NT; ++t)
        scratch[(w * NT + t) * 32 + lane] = unpack_sum(acc2[t]);
    __syncthreads();

    for (int n = w; n < NROWS; n += 16) {
        const int nng = n / NT, tt = n % NT;
        float s = 0.0f;
        #pragma unroll
        for (int kk = 0; kk < KG; ++kk)
            s += scratch[((kk * NG + nng) * NT + tt) * 32 + lane];
        if (ATOMIC_OUT) {
            atomicAdd(&dest[(size_t)(n0 + n) * 32 + lane], s);
        } else {
            s += __ldcg(bias + n0 + n);
            s = fmaxf(s, 0.0f);
            dest[(size_t)lane * ldo + n0 + n] = s;
        }
    }
    __syncthreads();
}

// ---- the one kernel ----------------------------------------------------------------
__global__ __launch_bounds__(512, 1) void fused_kernel(
    const float* __restrict__ img,
    const float* __restrict__ W1, const float* __restrict__ b1,
    const float* __restrict__ W2, const float* __restrict__ b2,
    const float* __restrict__ W3, const float* __restrict__ b3,
    float* __restrict__ out,
    float* __restrict__ hraw, float* __restrict__ histP,
    float* __restrict__ x1T, float* __restrict__ x2T) {

    extern __shared__ float buf[];          // W tiles + reduce scratch
    __shared__ float sh[3 * 1024];          // private hist bins / normalize stash
    __shared__ float ssum[3];
    __shared__ int   s_last;

    const int cta = blockIdx.x;
    const int tid = threadIdx.x;
    const int im   = cta >> 2;              // image 0..31
    const int part = cta & 3;               // quarter 0..3

    // ---- batched pixel loads first (256 px per CTA, threads 0..255) --------
    float r0 = 0, g0 = 0, l0 = 0;
    if (tid < 256) {
        const int p = part * 256 + tid;
        const float* base = img + (size_t)im * 3 * 262144;
        const int off = ((p >> 5) * 16) * 512 + ((p & 31) * 16);
        r0 = __ldcg(base + off);
        g0 = __ldcg(base + 262144 + off);
        l0 = __ldcg(base + 524288 + off);
    }

    // ---- stage W tiles (every CTA, its own fc assignments) ------------------
    stage_tile<32, 768>(buf + W1_OFF,
                        W1 + (size_t)((cta & 31) * 32) * 3072 + (cta >> 5) * 768, 3072);
    stage_tile<16, 256>(buf + W2_OFF,
                        W2 + (size_t)((cta & 31) * 16) * 1024 + (cta >> 5) * 256, 1024);
    stage_tile<2, 512>(buf + W3_OFF, W3 + (size_t)(cta * 2) * 512, 512);

    // ---- bias pre-init of accumulators --------------------------------------
    {
        const int idx = cta * 512 + tid;
        if (idx < 32768)       __stcg(&x1T[idx], __ldcg(b1 + (idx >> 5)));
        else if (idx < 49152)  { int j = idx - 32768; __stcg(&x2T[j], __ldcg(b2 + (j >> 5))); }
    }

    // ---- binning: private smem hist, then sparse atomic merge ---------------
    #pragma unroll
    for (int i = tid; i < 3072; i += 512) sh[i] = 0.0f;
    __syncthreads();

    if (tid < 256 && r0 > 0.0f && g0 > 0.0f && l0 > 0.0f) {
        float w  = sqrtf(r0 * r0 + g0 * g0 + l0 * l0);
        float lr = logf(r0), lg = logf(g0), lb = logf(l0);
        hist_add(&sh[0],    lr - lb, lr - lg, w);
        hist_add(&sh[1024], lg - lb, lg - lr, w);
        hist_add(&sh[2048], lb - lg, lb - lr, w);
    }
    __syncthreads();

    #pragma unroll
    for (int i = tid; i < 3072; i += 512) {
        float v = sh[i];
        if (v != 0.0f)
            atomicAdd(&hraw[(i >> 1) * 64 + im * 2 + (i & 1)], v);
    }

    __threadfence();
    __syncthreads();
    if (tid == 0) {
        unsigned old = atomicAdd(&g_ticket[im], 1u);
        s_last = (old == 3u) ? 1 : 0;
        if (old == 3u) g_ticket[im] = 0;     // reset for next replay
    }
    __syncthreads();

    if (s_last) {
        // last CTA of this image: normalize. Acquire merged bins.
        __threadfence();
        if (tid < 3) ssum[tid] = 0.0f;
        #pragma unroll
        for (int i = tid; i < 3072; i += 512) {
            float v = __ldcg(&hraw[(i >> 1) * 64 + im * 2 + (i & 1)]);
            sh[i] = v;
            __stcg(&hraw[(i >> 1) * 64 + im * 2 + (i & 1)], 0.0f);   // re-zero
        }
        __syncthreads();

        float cs[3] = {0.f, 0.f, 0.f};
        #pragma unroll
        for (int i = tid; i < 3072; i += 512) cs[i >> 10] += sh[i];
        #pragma unroll
        for (int c = 0; c < 3; ++c) {
            float s = cs[c];
            #pragma unroll
            for (int o = 16; o > 0; o >>= 1) s += __shfl_down_sync(0xffffffffu, s, o);
            if ((tid & 31) == 0 && s != 0.0f) atomicAdd(&ssum[c], s);
        }
        __syncthreads();

        #pragma unroll
        for (int i = tid; i < 3072; i += 512) {
            float v = sqrtf(sh[i] / ssum[i >> 10]);
            __stcg(&histP[(i >> 1) * 64 + im * 2 + (i & 1)], v);
        }
    }

    grid_barrier();

    // =========== fc1: 1024 x 3072 — 32 nb(32 n) x 4 kb(768 K) ==================
    fc_compute<768, 32, 16, 2, 8, 2, false, true, true>(
        histP, buf + W1_OFF, nullptr, x1T, 0, buf, (cta & 31) * 32, (cta >> 5) * 768);
    grid_barrier();

    // =========== fc2: 512 x 1024 — 32 nb(16 n) x 4 kb(256 K), relu-in ==========
    fc_compute<256, 16, 8, 2, 8, 1, true, false, true>(
        x1T, buf + W2_OFF, nullptr, x2T, 0, buf, (cta & 31) * 16, (cta >> 5) * 256);
    grid_barrier();

    // =========== fc3: 256 x 512 — 2 neurons/CTA, full K, relu-in, direct out ====
    fc_compute<512, 2, 2, 1, 16, 1, true, false, false>(
        x2T, buf + W3_OFF, b3, out, 256, buf, cta * 2, 0);
}

extern "C" void kernel_launch(void* const* d_in, const int* in_sizes, int n_in,
                              void* d_out, int out_size) {
    const float* inp = (const float*)d_in[0];
    const float* W1  = (const float*)d_in[1];
    const float* b1  = (const float*)d_in[2];
    const float* W2  = (const float*)d_in[3];
    const float* b2  = (const float*)d_in[4];
    const float* W3  = (const float*)d_in[5];
    const float* b3  = (const float*)d_in[6];
    float* out = (float*)d_out;

    float* hraw;  cudaGetSymbolAddress((void**)&hraw,  g_hraw);
    float* histP; cudaGetSymbolAddress((void**)&histP, g_histP);
    float* x1T;   cudaGetSymbolAddress((void**)&x1T,   g_x1T);
    float* x2T;   cudaGetSymbolAddress((void**)&x2T,   g_x2T);

    cudaFuncSetAttribute(fused_kernel,
                         cudaFuncAttributeMaxDynamicSharedMemorySize, SMEM_BYTES);
    fused_kernel<<<NCTA, 512, SMEM_BYTES>>>(inp, W1, b1, W2, b2, W3, b3, out,
                                            hraw, histP, x1T, x2T);
}

// round 14
// speedup vs baseline: 1.2615x; 1.2615x over previous
#include <cuda_runtime.h>
#include <math.h>

// ---------------------------------------------------------------------------
// SimplifiedIFEBranch — R14: R7 pipeline at 2 CTAs/SM: 256 CTAs x 512 thr
// (8 warps/SMSP latency hiding), halved tiles (W1 16x768=48KB), NT=8,
// <=64 regs. Same FFMA2 inner loop, 3 grid barriers, hist in CTAs 0..31.
// ---------------------------------------------------------------------------

#define NBINS 32
#define NCTA  256

// dynamic smem layout (floats)
#define W1_OFF 0            // 16 x 768 = 12288 floats (48 KB)
#define W2_OFF 12288        //  8 x 256 =  2048 floats ( 8 KB)
#define W3_OFF 14336        //  1 x 512 =   512 floats ( 2 KB)
#define SMEM_FLOATS 14848
#define SMEM_BYTES  (SMEM_FLOATS * 4)      // 59392 B -> 2 CTAs/SM

__device__ __forceinline__ float c_LO() { return (float)(-3.2 - (6.4 / 256.0) / 2.0); }
__device__ __forceinline__ float c_HI() { return (float)( 3.2 - (6.4 / 256.0) / 2.0); }
__device__ __forceinline__ float c_BW() {
    return (float)(((3.2 - (6.4 / 256.0) / 2.0) - (-3.2 - (6.4 / 256.0) / 2.0)) / 32.0);
}

// Scratch (__device__ globals; no allocation allowed)
__device__ float g_histP[3072 * 32];   // pair-packed: [(k/2)][b][2]
__device__ float g_x1T[1024 * 32];     // [n][b] accum, bias-preinit
__device__ float g_x2T[512 * 32];
__device__ unsigned int g_bar_count = 0;
__device__ unsigned int g_bar_gen   = 0;

// ---- packed f32x2 helpers ---------------------------------------------------
__device__ __forceinline__ unsigned long long pack2(float x, float y) {
    unsigned long long r;
    asm("mov.b64 %0, {%1, %2};" : "=l"(r) : "f"(x), "f"(y));
    return r;
}
__device__ __forceinline__ void ffma2(unsigned long long& d,
                                      unsigned long long a, unsigned long long b) {
    asm("fma.rn.f32x2 %0, %1, %2, %0;" : "+l"(d) : "l"(a), "l"(b));
}
__device__ __forceinline__ float unpack_sum(unsigned long long p) {
    float lo, hi;
    asm("mov.b64 {%0, %1}, %2;" : "=f"(lo), "=f"(hi) : "l"(p));
    return lo + hi;
}

// ---- software grid barrier ----------------------------------------------------
__device__ __forceinline__ void grid_barrier() {
    __syncthreads();
    if (threadIdx.x == 0) {
        unsigned gen = *(volatile unsigned*)&g_bar_gen;
        __threadfence();
        unsigned old = atomicAdd(&g_bar_count, 1u);
        if (old == NCTA - 1) {
            g_bar_count = 0;
            __threadfence();
            atomicAdd(&g_bar_gen, 1u);
        } else {
            while (*(volatile unsigned*)&g_bar_gen == gen) { __nanosleep(32); }
        }
        __threadfence();
    }
    __syncthreads();
}

// ---- histogram helper -----------------------------------------------------------
__device__ __forceinline__ void hist_add(float* h, float Iu, float Iv, float w) {
    const float LO = c_LO(), HI = c_HI(), BW = c_BW();
    if (Iu >= LO && Iu <= HI && Iv >= LO && Iv <= HI) {
        int iu = (int)floorf((Iu - LO) / BW);
        int iv = (int)floorf((Iv - LO) / BW);
        iu = min(max(iu, 0), NBINS - 1);
        iv = min(max(iv, 0), NBINS - 1);
        atomicAdd(&h[iu * NBINS + iv], w);
    }
}

// ---- coalesced W tile stage (global -> smem), each element once ----------------
template <int ROWS, int COLS>
__device__ __forceinline__ void stage_tile(float* dst, const float* src, int ld) {
    constexpr int F4 = ROWS * COLS / 4;
    constexpr int RF = COLS / 4;
    #pragma unroll
    for (int f = threadIdx.x; f < F4; f += 512) {
        const int row = f / RF, col = f - row * RF;
        float4 v = __ldcg(reinterpret_cast<const float4*>(src + (size_t)row * ld + col * 4));
        reinterpret_cast<float4*>(dst)[f] = v;
    }
}

// ---- FC compute (W tile already in smem) ----------------------------------------
// 16 warps = KG k-groups x NG n-groups; NT neurons per warp; lane = batch.
template <int KS, int NROWS, int NT, int NG, int KG, int HALVES,
          bool RELU_IN, bool PACKED_A, bool ATOMIC_OUT>
__device__ __forceinline__ void fc_compute(const float* __restrict__ AT,
                                           const float* wtile,
                                           const float* __restrict__ bias,
                                           float* __restrict__ dest, int ldo,
                                           float* scratch, int n0, int K0) {
    constexpr int CH = KS / KG;
    constexpr int NK = CH / HALVES;
    const int tid  = threadIdx.x;
    const int lane = tid & 31;
    const int w    = tid >> 5;
    const int kg   = w / NG;
    const int ng   = w % NG;

    unsigned long long acc2[NT];
    #pragma unroll
    for (int t = 0; t < NT; ++t) acc2[t] = 0ull;

    const int kbase = K0 + kg * CH;
    const float* wrow0 = wtile + (size_t)(ng * NT) * KS + kg * CH;

    #pragma unroll
    for (int h = 0; h < HALVES; ++h) {
        const int kh = kbase + h * NK;
        unsigned long long ap[NK / 2];
        if (PACKED_A) {
            const unsigned long long* src =
                reinterpret_cast<const unsigned long long*>(AT)
                + (size_t)(kh >> 1) * 32 + lane;
            #pragma unroll
            for (int j = 0; j < NK / 2; ++j) ap[j] = __ldcg(src + (size_t)j * 32);
        } else {
            #pragma unroll
            for (int j = 0; j < NK / 2; ++j) {
                float a0 = __ldcg(AT + (size_t)(kh + 2 * j) * 32 + lane);
                float a1 = __ldcg(AT + (size_t)(kh + 2 * j + 1) * 32 + lane);
                if (RELU_IN) { a0 = fmaxf(a0, 0.f); a1 = fmaxf(a1, 0.f); }
                ap[j] = pack2(a0, a1);
            }
        }
        #pragma unroll
        for (int j2 = 0; j2 < NK / 4; ++j2) {
            #pragma unroll
            for (int t = 0; t < NT; ++t) {
                ulonglong2 wv = *reinterpret_cast<const ulonglong2*>(
                    wrow0 + (size_t)t * KS + h * NK + 4 * j2);
                ffma2(acc2[t], wv.x, ap[2 * j2]);
                ffma2(acc2[t], wv.y, ap[2 * j2 + 1]);
            }
        }
    }
    __syncthreads();                        // wtile reads done; scratch may alias

    #pragma unroll
    for (int t = 0; t < NT; ++t)
        scratch[(w * NT + t) * 32 + lane] = unpack_sum(acc2[t]);
    __syncthreads();

    for (int n = w; n < NROWS; n += 16) {
        const int nng = n / NT, tt = n % NT;
        float s = 0.0f;
        #pragma unroll
        for (int kk = 0; kk < KG; ++kk)
            s += scratch[((kk * NG + nng) * NT + tt) * 32 + lane];
        if (ATOMIC_OUT) {
            atomicAdd(&dest[(size_t)(n0 + n) * 32 + lane], s);
        } else {
            s += __ldcg(bias + n0 + n);
            s = fmaxf(s, 0.0f);
            dest[(size_t)lane * ldo + n0 + n] = s;
        }
    }
    __syncthreads();
}

// ---- the one kernel ----------------------------------------------------------------
__global__ __launch_bounds__(512, 2) void fused_kernel(
    const float* __restrict__ img,
    const float* __restrict__ W1, const float* __restrict__ b1,
    const float* __restrict__ W2, const float* __restrict__ b2,
    const float* __restrict__ W3, const float* __restrict__ b3,
    float* __restrict__ out,
    float* __restrict__ histP, float* __restrict__ x1T, float* __restrict__ x2T) {

    extern __shared__ float buf[];          // W tiles + reduce scratch
    __shared__ float sh[3 * 1024];          // hist bins (static, coexists)
    __shared__ float ssum[3];

    const int cta = blockIdx.x;
    const int tid = threadIdx.x;

    // ---- hist pixel loads first (latency hidden under staging) -------------
    float r0 = 0, g0 = 0, l0 = 0, r1 = 0, g1 = 0, l1 = 0;
    if (cta < 32) {
        const float* base = img + (size_t)cta * 3 * 262144;
        const int p0 = tid, p1 = tid + 512;
        const int off0 = ((p0 >> 5) * 16) * 512 + ((p0 & 31) * 16);
        const int off1 = ((p1 >> 5) * 16) * 512 + ((p1 & 31) * 16);
        r0 = __ldcg(base + off0);
        g0 = __ldcg(base + 262144 + off0);
        l0 = __ldcg(base + 524288 + off0);
        r1 = __ldcg(base + off1);
        g1 = __ldcg(base + 262144 + off1);
        l1 = __ldcg(base + 524288 + off1);
    }

    // ---- stage this CTA's W tiles -------------------------------------------
    // fc1: nb = cta & 63 (16 n), kb = cta >> 6 (768 K)
    stage_tile<16, 768>(buf + W1_OFF,
                        W1 + (size_t)((cta & 63) * 16) * 3072 + (cta >> 6) * 768, 3072);
    // fc2: nb = cta & 63 (8 n), kb = cta >> 6 (256 K)
    stage_tile<8, 256>(buf + W2_OFF,
                       W2 + (size_t)((cta & 63) * 8) * 1024 + (cta >> 6) * 256, 1024);
    // fc3: 1 n per CTA, full K=512
    stage_tile<1, 512>(buf + W3_OFF, W3 + (size_t)cta * 512, 512);

    // ---- bias pre-init of accumulators (49152 over 131072 threads) ----------
    {
        const int idx = cta * 512 + tid;
        if (idx < 32768)       __stcg(&x1T[idx], __ldcg(b1 + (idx >> 5)));
        else if (idx < 49152)  { int j = idx - 32768; __stcg(&x2T[j], __ldcg(b2 + (j >> 5))); }
    }

    // ---- histogram (CTAs 0..31) ----------------------------------------------
    if (cta < 32) {
        const int b = cta;
        #pragma unroll
        for (int i = tid; i < 3072; i += 512) sh[i] = 0.0f;
        if (tid < 3) ssum[tid] = 0.0f;
        __syncthreads();

        if (r0 > 0.0f && g0 > 0.0f && l0 > 0.0f) {
            float w  = sqrtf(r0 * r0 + g0 * g0 + l0 * l0);
            float lr = logf(r0), lg = logf(g0), lb = logf(l0);
            hist_add(&sh[0],    lr - lb, lr - lg, w);
            hist_add(&sh[1024], lg - lb, lg - lr, w);
            hist_add(&sh[2048], lb - lg, lb - lr, w);
        }
        if (r1 > 0.0f && g1 > 0.0f && l1 > 0.0f) {
            float w  = sqrtf(r1 * r1 + g1 * g1 + l1 * l1);
            float lr = logf(r1), lg = logf(g1), lb = logf(l1);
            hist_add(&sh[0],    lr - lb, lr - lg, w);
            hist_add(&sh[1024], lg - lb, lg - lr, w);
            hist_add(&sh[2048], lb - lg, lb - lr, w);
        }
        __syncthreads();

        #pragma unroll
        for (int c = 0; c < 3; ++c) {
            float s = sh[c * 1024 + tid] + sh[c * 1024 + tid + 512];
            #pragma unroll
            for (int o = 16; o > 0; o >>= 1) s += __shfl_down_sync(0xffffffffu, s, o);
            if ((tid & 31) == 0) atomicAdd(&ssum[c], s);
        }
        __syncthreads();

        // pair-packed write: histP[(k/2)*64 + b*2 + (k&1)]
        #pragma unroll
        for (int i = tid; i < 1024; i += 512) {
            #pragma unroll
            for (int c = 0; c < 3; ++c) {
                const int k = c * 1024 + i;
                float v = sqrtf(sh[c * 1024 + i] / ssum[c]);
                __stcg(&histP[(k >> 1) * 64 + b * 2 + (k & 1)], v);
            }
        }
    }

    grid_barrier();

    // ===== fc1: 1024 x 3072 — 64 nb(16 n) x 4 kb(768 K); NT=8, H=6 =============
    fc_compute<768, 16, 8, 2, 8, 6, false, true, true>(
        histP, buf + W1_OFF, nullptr, x1T, 0, buf, (cta & 63) * 16, (cta >> 6) * 768);
    grid_barrier();

    // ===== fc2: 512 x 1024 — 64 nb(8 n) x 4 kb(256 K); NT=4, H=2, relu-in ======
    fc_compute<256, 8, 4, 2, 8, 2, true, false, true>(
        x1T, buf + W2_OFF, nullptr, x2T, 0, buf, (cta & 63) * 8, (cta >> 6) * 256);
    grid_barrier();

    // ===== fc3: 256 x 512 — 1 n/CTA, full K; KG=16, H=2, relu-in, direct ======
    fc_compute<512, 1, 1, 1, 16, 2, true, false, false>(
        x2T, buf + W3_OFF, b3, out, 256, buf, cta, 0);
}

extern "C" void kernel_launch(void* const* d_in, const int* in_sizes, int n_in,
                              void* d_out, int out_size) {
    const float* inp = (const float*)d_in[0];
    const float* W1  = (const float*)d_in[1];
    const float* b1  = (const float*)d_in[2];
    const float* W2  = (const float*)d_in[3];
    const float* b2  = (const float*)d_in[4];
    const float* W3  = (const float*)d_in[5];
    const float* b3  = (const float*)d_in[6];
    float* out = (float*)d_out;

    float* histP; cudaGetSymbolAddress((void**)&histP, g_histP);
    float* x1T;   cudaGetSymbolAddress((void**)&x1T,   g_x1T);
    float* x2T;   cudaGetSymbolAddress((void**)&x2T,   g_x2T);

    cudaFuncSetAttribute(fused_kernel,
                         cudaFuncAttributeMaxDynamicSharedMemorySize, SMEM_BYTES);
    fused_kernel<<<NCTA, 512, SMEM_BYTES>>>(inp, W1, b1, W2, b2, W3, b3, out,
                                            histP, x1T, x2T);
}